// round 4
// baseline (speedup 1.0000x reference)
#include <cuda_runtime.h>
#include <math.h>

#define MAXN 50000

// scratch (device globals — no allocation allowed)
__device__ float g_chis[MAXN];
__device__ float g_sigA[MAXN];
__device__ float g_epsA[MAXN];
__device__ float g_w[MAXN * 16];
__device__ float g_scal[2];   // pot, vdw

// weights in constant memory (separate const port -> no L1 wavefront cost)
__constant__ float cWc1[64 * 16];
__constant__ float cWs1[64 * 32];
__constant__ float cWe1[64 * 32];
__constant__ float cWc2[16];
__constant__ float cWs2[32];
__constant__ float cWe2[32];
__constant__ float cWw1[17 * 16];
__constant__ float cWx1[80 * 32];
__constant__ float cWx2[32 * 32];
__constant__ float cWx3[32 * 32];

__device__ __forceinline__ float siluf(float z) {
    return z / (1.0f + __expf(-z));
}
__device__ __forceinline__ float sigmf(float z) {
    return 1.0f / (1.0f + __expf(-z));
}

// ---- packed f32x2 helpers (SASS FFMA2 — only reachable via PTX) ----
__device__ __forceinline__ unsigned long long dup2(float v) {
    unsigned long long r;
    asm("mov.b64 %0, {%1, %1};" : "=l"(r) : "f"(v));
    return r;
}
__device__ __forceinline__ unsigned long long pk2(float a, float b) {
    unsigned long long r;
    asm("mov.b64 %0, {%1, %2};" : "=l"(r) : "f"(a), "f"(b));
    return r;
}
__device__ __forceinline__ void ffma2(unsigned long long& d,
                                      unsigned long long a,
                                      unsigned long long b) {
    asm("fma.rn.f32x2 %0, %1, %2, %0;" : "+l"(d) : "l"(a), "l"(b));
}
__device__ __forceinline__ float2 unpk(unsigned long long v) {
    float2 f;
    asm("mov.b64 {%0, %1}, %2;" : "=f"(f.x), "=f"(f.y) : "l"(v));
    return f;
}

__global__ void k_zero(int N) {
    int i = blockIdx.x * blockDim.x + threadIdx.x;
    if (i < N) { g_chis[i] = 0.f; g_sigA[i] = 0.f; g_epsA[i] = 0.f; }
    if (i < 2) g_scal[i] = 0.f;
}

// ---------------------------------------------------------------------------
// Phase 1: per-edge fused chi/sigma/eps MLPs (64 -> 80 hidden -> 3 scalars),
// scatter-add. Weights from __constant__; input scale 1/sqrt(64) folded
// into the activation; output scales folded into the epilogue.
// ---------------------------------------------------------------------------
__global__ __launch_bounds__(256) void k_phase1(
    const float* __restrict__ x, const int* __restrict__ senders, int E)
{
    int e = blockIdx.x * 256 + threadIdx.x;
    if (e >= E) return;

    unsigned long long acc[40];
#pragma unroll
    for (int i = 0; i < 40; i++) acc[i] = 0ull;

    const float4* x4 = reinterpret_cast<const float4*>(x) + (size_t)e * 16;
    const float2* wc = reinterpret_cast<const float2*>(cWc1);
    const float2* ws = reinterpret_cast<const float2*>(cWs1);
    const float2* we = reinterpret_cast<const float2*>(cWe1);

#pragma unroll 1
    for (int kc = 0; kc < 16; kc++) {
        float4 xv = x4[kc];
#pragma unroll
        for (int sub = 0; sub < 4; sub++) {
            int k = kc * 4 + sub;
            float xs = (sub == 0) ? xv.x : (sub == 1) ? xv.y
                     : (sub == 2) ? xv.z : xv.w;
            unsigned long long xd = dup2(xs * 0.125f);   // 1/sqrt(64)
#pragma unroll
            for (int j = 0; j < 8; j++) {
                float2 w = wc[k * 8 + j];
                ffma2(acc[j], xd, pk2(w.x, w.y));
            }
#pragma unroll
            for (int j = 0; j < 16; j++) {
                float2 w = ws[k * 16 + j];
                ffma2(acc[8 + j], xd, pk2(w.x, w.y));
            }
#pragma unroll
            for (int j = 0; j < 16; j++) {
                float2 w = we[k * 16 + j];
                ffma2(acc[24 + j], xd, pk2(w.x, w.y));
            }
        }
    }

    float chi = 0.f, sg = 0.f, ep = 0.f;
#pragma unroll
    for (int j = 0; j < 8; j++) {
        float2 f = unpk(acc[j]);
        chi += siluf(f.x) * cWc2[2 * j] + siluf(f.y) * cWc2[2 * j + 1];
    }
#pragma unroll
    for (int j = 0; j < 16; j++) {
        float2 f = unpk(acc[8 + j]);
        sg += siluf(f.x) * cWs2[2 * j] + siluf(f.y) * cWs2[2 * j + 1];
    }
#pragma unroll
    for (int j = 0; j < 16; j++) {
        float2 f = unpk(acc[24 + j]);
        ep += siluf(f.x) * cWe2[2 * j] + siluf(f.y) * cWe2[2 * j + 1];
    }
    chi *= 0.25f;                     // 1/sqrt(16)
    sg  *= 0.17677669529663689f;      // 1/sqrt(32)
    ep  *= 0.17677669529663689f;

    int s = senders[e];
    atomicAdd(&g_chis[s], chi);
    atomicAdd(&g_sigA[s], sg);
    atomicAdd(&g_epsA[s], ep);
}

// ---------------------------------------------------------------------------
// Phase 2: per-node charges / pot / vdw / w embedding (W_w1 from constant;
// 1/sqrt(17) folded into the inputs).
// ---------------------------------------------------------------------------
__global__ __launch_bounds__(256) void k_nodes(
    const int* __restrict__ species, const float* __restrict__ radius,
    const float* __restrict__ hardness, const float* __restrict__ charge_embed,
    float* __restrict__ out_charges, int N)
{
    int n = blockIdx.x * 256 + threadIdx.x;
    float potc = 0.f, vdwc = 0.f;
    if (n < N) {
        int sp = species[n];
        float gamma = fmaf(4.f, radius[sp], 0.5f);
        float hv = hardness[sp];
        float hard = fmaxf(hv, 0.f) + log1pf(__expf(-fabsf(hv)));  // stable softplus
        float chis = g_chis[n];
        float q = -chis / hard;
        potc = 0.5f * (hard + 1.f / gamma) * q * q + chis * q;
        float sgv = sigmf(g_sigA[n]) * 0.15f + 0.15f;
        float epv = sigmf(g_epsA[n]) * 1.7f + 0.3f;
        vdwc = sgv * epv;
        out_charges[n] = q;

        const float s17 = 0.24253562503633297f;  // 1/sqrt(17)
        const float* ce = charge_embed + (size_t)sp * 16;
        float wv[16];
        float qs = q * s17;
#pragma unroll
        for (int j = 0; j < 16; j++) wv[j] = qs * cWw1[j];
#pragma unroll
        for (int i = 0; i < 16; i++) {
            float c = ce[i] * s17;
#pragma unroll
            for (int j = 0; j < 16; j++)
                wv[j] = fmaf(c, cWw1[(1 + i) * 16 + j], wv[j]);
        }
        float4* wout = reinterpret_cast<float4*>(g_w) + (size_t)n * 4;
#pragma unroll
        for (int j = 0; j < 4; j++)
            wout[j] = make_float4(wv[4 * j], wv[4 * j + 1], wv[4 * j + 2], wv[4 * j + 3]);
    }
#pragma unroll
    for (int off = 16; off > 0; off >>= 1) {
        potc += __shfl_down_sync(0xffffffffu, potc, off);
        vdwc += __shfl_down_sync(0xffffffffu, vdwc, off);
    }
    if ((threadIdx.x & 31) == 0) {
        atomicAdd(&g_scal[0], potc);
        atomicAdd(&g_scal[1], vdwc);
    }
}

// ---------------------------------------------------------------------------
// Phase 3: per-edge 80->32->32->32 MLP, envelope, output + V copy + pot/vdw
// finalize. Weights from __constant__; layer input scales folded into
// activations.
// ---------------------------------------------------------------------------
__global__ __launch_bounds__(256) void k_phase3(
    const float* __restrict__ x, const float* __restrict__ vectors,
    const float* __restrict__ V, const int* __restrict__ senders,
    float* __restrict__ out_x, float* __restrict__ out_V,
    float* __restrict__ out_pv, int E)
{
    if (blockIdx.x == 0 && threadIdx.x == 0) {
        out_pv[0] = g_scal[0];  // pot (final after k_nodes)
        out_pv[1] = g_scal[1];  // vdw
    }

    int e = blockIdx.x * 256 + threadIdx.x;
    if (e >= E) return;

    const float s80 = 0.11180339887498949f;   // 1/sqrt(80)
    const float s32 = 0.17677669529663689f;   // 1/sqrt(32)

    unsigned long long acc[16];
#pragma unroll
    for (int j = 0; j < 16; j++) acc[j] = 0ull;

    const float2* w1 = reinterpret_cast<const float2*>(cWx1);
    const float2* w2 = reinterpret_cast<const float2*>(cWx2);
    const float2* w3 = reinterpret_cast<const float2*>(cWx3);

    // layer 1, rows 0..63: x (scaled by 1/sqrt(80))
    const float4* x4 = reinterpret_cast<const float4*>(x) + (size_t)e * 16;
#pragma unroll 1
    for (int kc = 0; kc < 16; kc++) {
        float4 xv = x4[kc];
#pragma unroll
        for (int sub = 0; sub < 4; sub++) {
            int k = kc * 4 + sub;
            float xs = (sub == 0) ? xv.x : (sub == 1) ? xv.y
                     : (sub == 2) ? xv.z : xv.w;
            unsigned long long xd = dup2(xs * s80);
#pragma unroll
            for (int j = 0; j < 16; j++) {
                float2 w = w1[k * 16 + j];
                ffma2(acc[j], xd, pk2(w.x, w.y));
            }
        }
    }
    // layer 1, rows 64..79: w[sender] (same layer scale)
    int s = senders[e];
    const float4* wn = reinterpret_cast<const float4*>(g_w) + (size_t)s * 4;
#pragma unroll
    for (int kc = 0; kc < 4; kc++) {
        float4 xv = wn[kc];
#pragma unroll
        for (int sub = 0; sub < 4; sub++) {
            int k = 64 + kc * 4 + sub;
            float xs = (sub == 0) ? xv.x : (sub == 1) ? xv.y
                     : (sub == 2) ? xv.z : xv.w;
            unsigned long long xd = dup2(xs * s80);
#pragma unroll
            for (int j = 0; j < 16; j++) {
                float2 w = w1[k * 16 + j];
                ffma2(acc[j], xd, pk2(w.x, w.y));
            }
        }
    }

    float h1[32];
#pragma unroll
    for (int j = 0; j < 16; j++) {
        float2 f = unpk(acc[j]);
        h1[2 * j]     = siluf(f.x) * s32;   // fold next layer's input scale
        h1[2 * j + 1] = siluf(f.y) * s32;
    }

    // layer 2
#pragma unroll
    for (int j = 0; j < 16; j++) acc[j] = 0ull;
#pragma unroll 2
    for (int k = 0; k < 32; k++) {
        unsigned long long xd = dup2(h1[k]);
#pragma unroll
        for (int j = 0; j < 16; j++) {
            float2 w = w2[k * 16 + j];
            ffma2(acc[j], xd, pk2(w.x, w.y));
        }
    }
#pragma unroll
    for (int j = 0; j < 16; j++) {
        float2 f = unpk(acc[j]);
        h1[2 * j]     = siluf(f.x) * s32;
        h1[2 * j + 1] = siluf(f.y) * s32;
    }

    // layer 3 (no activation)
#pragma unroll
    for (int j = 0; j < 16; j++) acc[j] = 0ull;
#pragma unroll 2
    for (int k = 0; k < 32; k++) {
        unsigned long long xd = dup2(h1[k]);
#pragma unroll
        for (int j = 0; j < 16; j++) {
            float2 w = w3[k * 16 + j];
            ffma2(acc[j], xd, pk2(w.x, w.y));
        }
    }

    // envelope (MAX_RADIUS = 1, p = 6)
    const float* vp = vectors + (size_t)e * 3;
    float vx = vp[0], vy = vp[1], vz = vp[2];
    float u = sqrtf(vx * vx + vy * vy + vz * vz);
    float env = 0.f;
    if (u < 1.f) {
        float u2 = u * u;
        float u3 = u2 * u;
        float u6 = u3 * u3;
        env = 1.f + u6 * (-28.f + u * (48.f - 21.f * u));
    }

    float4* ox = reinterpret_cast<float4*>(out_x) + (size_t)e * 8;
#pragma unroll
    for (int j = 0; j < 8; j++) {
        float2 f0 = unpk(acc[2 * j]);
        float2 f1 = unpk(acc[2 * j + 1]);
        ox[j] = make_float4(env * f0.x, env * f0.y, env * f1.x, env * f1.y);
    }

    const float4* vin = reinterpret_cast<const float4*>(V) + (size_t)e * 4;
    float4* ov = reinterpret_cast<float4*>(out_V) + (size_t)e * 4;
#pragma unroll
    for (int j = 0; j < 4; j++) ov[j] = vin[j];
}

// ---------------------------------------------------------------------------
// Launch. Output layout: x_out[E*32] | V[E*16] | charges[N] | pot | vdw
// ---------------------------------------------------------------------------
extern "C" void kernel_launch(void* const* d_in, const int* in_sizes, int n_in,
                              void* d_out, int out_size) {
    const float* vectors = (const float*)d_in[0];
    const float* x       = (const float*)d_in[1];
    const float* V       = (const float*)d_in[2];
    const int*   senders = (const int*)d_in[3];
    const int*   species = (const int*)d_in[4];
    const float* radius  = (const float*)d_in[5];
    const float* hardness= (const float*)d_in[6];
    const float* cembed  = (const float*)d_in[7];

    const int E = in_sizes[3];
    const int N = in_sizes[4];

    // weights -> constant bank (async D2D, graph-capturable)
    cudaMemcpyToSymbolAsync(cWc1, d_in[8],  64 * 16 * 4, 0, cudaMemcpyDeviceToDevice, 0);
    cudaMemcpyToSymbolAsync(cWc2, d_in[9],  16 * 4,      0, cudaMemcpyDeviceToDevice, 0);
    cudaMemcpyToSymbolAsync(cWs1, d_in[10], 64 * 32 * 4, 0, cudaMemcpyDeviceToDevice, 0);
    cudaMemcpyToSymbolAsync(cWs2, d_in[11], 32 * 4,      0, cudaMemcpyDeviceToDevice, 0);
    cudaMemcpyToSymbolAsync(cWe1, d_in[12], 64 * 32 * 4, 0, cudaMemcpyDeviceToDevice, 0);
    cudaMemcpyToSymbolAsync(cWe2, d_in[13], 32 * 4,      0, cudaMemcpyDeviceToDevice, 0);
    cudaMemcpyToSymbolAsync(cWw1, d_in[14], 17 * 16 * 4, 0, cudaMemcpyDeviceToDevice, 0);
    cudaMemcpyToSymbolAsync(cWx1, d_in[15], 80 * 32 * 4, 0, cudaMemcpyDeviceToDevice, 0);
    cudaMemcpyToSymbolAsync(cWx2, d_in[16], 32 * 32 * 4, 0, cudaMemcpyDeviceToDevice, 0);
    cudaMemcpyToSymbolAsync(cWx3, d_in[17], 32 * 32 * 4, 0, cudaMemcpyDeviceToDevice, 0);

    float* out = (float*)d_out;
    float* out_x       = out;
    float* out_V       = out + (size_t)E * 32;
    float* out_charges = out + (size_t)E * 48;
    float* out_pv      = out + (size_t)E * 48 + N;

    int nb_n = (N + 255) / 256;
    int nb_e = (E + 255) / 256;

    k_zero<<<nb_n, 256>>>(N);
    k_phase1<<<nb_e, 256>>>(x, senders, E);
    k_nodes<<<nb_n, 256>>>(species, radius, hardness, cembed, out_charges, N);
    k_phase3<<<nb_e, 256>>>(x, vectors, V, senders, out_x, out_V, out_pv, E);
}

// round 5
// speedup vs baseline: 1.8626x; 1.8626x over previous
#include <cuda_runtime.h>
#include <math.h>

#define MAXN 50000

// scratch (device globals — no allocation allowed)
__device__ float g_chis[MAXN];
__device__ float g_sigA[MAXN];
__device__ float g_epsA[MAXN];
__device__ float g_w[MAXN * 16];
__device__ float g_scal[2];   // pot, vdw

// ---- constant-bank weight slices (k-dim tails; heads live in smem) ----
__constant__ float cWc1[40 * 16];   // Wc1 rows 24..63
__constant__ float cWs1[40 * 32];   // Ws1 rows 24..63
__constant__ float cWe1[40 * 32];   // We1 rows 24..63
__constant__ float cWc2[16];
__constant__ float cWs2[32];
__constant__ float cWe2[32];
__constant__ float cWw1[17 * 16];
__constant__ float cX1[48 * 32];    // Wx1 rows 32..79
__constant__ float cX2[20 * 32];    // Wx2 rows 12..31
__constant__ float cX3[20 * 32];    // Wx3 rows 12..31

__device__ __forceinline__ float siluf(float z) {
    return __fdividef(z, 1.0f + __expf(-z));
}
__device__ __forceinline__ float sigmf(float z) {
    return __fdividef(1.0f, 1.0f + __expf(-z));
}

// ---- packed f32x2 helpers (SASS FFMA2 — only reachable via PTX) ----
__device__ __forceinline__ unsigned long long dup2(float v) {
    unsigned long long r;
    asm("mov.b64 %0, {%1, %1};" : "=l"(r) : "f"(v));
    return r;
}
__device__ __forceinline__ void ffma2(unsigned long long& d,
                                      unsigned long long a,
                                      unsigned long long b) {
    asm("fma.rn.f32x2 %0, %1, %2, %0;" : "+l"(d) : "l"(a), "l"(b));
}
__device__ __forceinline__ float2 unpk(unsigned long long v) {
    float2 f;
    asm("mov.b64 {%0, %1}, %2;" : "=f"(f.x), "=f"(f.y) : "l"(v));
    return f;
}
__device__ __forceinline__ float sel4(float4 v, int sub) {
    return (sub == 0) ? v.x : (sub == 1) ? v.y : (sub == 2) ? v.z : v.w;
}

__global__ void k_zero(int N) {
    int i = blockIdx.x * blockDim.x + threadIdx.x;
    if (i < N) { g_chis[i] = 0.f; g_sigA[i] = 0.f; g_epsA[i] = 0.f; }
    if (i < 2) g_scal[i] = 0.f;
}

// ---------------------------------------------------------------------------
// Phase 1: per-edge fused chi/sigma/eps MLPs (64 -> 80 hidden -> 3 scalars).
// M=2 edges per thread; hidden split in halves across warp-groups (sel);
// weights: k<24 from smem (broadcast), k>=24 from constant bank.
// ---------------------------------------------------------------------------
__global__ __launch_bounds__(256) void k_phase1(
    const float* __restrict__ x, const int* __restrict__ senders,
    const float* __restrict__ Wc1, const float* __restrict__ Ws1,
    const float* __restrict__ We1, int E)
{
    __shared__ __align__(16) float sW[24 * 80];   // [k][h], unscaled
    for (int i = threadIdx.x; i < 24 * 80; i += 256) {
        int k = i / 80, h = i - (i / 80) * 80;
        float v;
        if (h < 16)      v = Wc1[k * 16 + h];
        else if (h < 48) v = Ws1[k * 32 + (h - 16)];
        else             v = We1[k * 32 + (h - 48)];
        sW[i] = v;
    }
    __syncthreads();

    int lane = threadIdx.x & 127;
    int sel  = threadIdx.x >> 7;        // warp-uniform: warps 0-3 sel=0, 4-7 sel=1
    int e0 = blockIdx.x * 256 + lane;
    if (e0 >= E) return;
    int e1 = e0 + 128;
    bool has1 = (e1 < E);

    const float s64 = 0.125f;                    // 1/sqrt(64)
    const float s32 = 0.17677669529663689f;      // 1/sqrt(32)

    // acc[0..19]: edge0 hidden pairs (sel*40 + 2j, +2j+1); acc[20..39]: edge1
    unsigned long long acc[40];
#pragma unroll
    for (int i = 0; i < 40; i++) acc[i] = 0ull;

    const float4* x0 = reinterpret_cast<const float4*>(x) + (size_t)e0 * 16;
    const float4* x1 = reinterpret_cast<const float4*>(x) + (size_t)(has1 ? e1 : e0) * 16;

    // ---- k = 0..23 from smem ----
#pragma unroll 1
    for (int kc = 0; kc < 6; kc++) {
        float4 a0 = x0[kc], a1 = x1[kc];
#pragma unroll
        for (int sub = 0; sub < 4; sub++) {
            int k = kc * 4 + sub;
            unsigned long long xd0 = dup2(sel4(a0, sub) * s64);
            unsigned long long xd1 = dup2(sel4(a1, sub) * s64);
            const ulonglong2* w =
                reinterpret_cast<const ulonglong2*>(sW + k * 80 + sel * 40);
#pragma unroll
            for (int j = 0; j < 10; j++) {
                ulonglong2 wv = w[j];
                ffma2(acc[2 * j],          xd0, wv.x);
                ffma2(acc[2 * j + 1],      xd0, wv.y);
                ffma2(acc[20 + 2 * j],     xd1, wv.x);
                ffma2(acc[20 + 2 * j + 1], xd1, wv.y);
            }
        }
    }

    // ---- k = 24..63 from constant bank (warp-uniform addresses) ----
    if (sel == 0) {
        // hidden 0..39 = Wc1 all (16) + Ws1 cols 0..23
#pragma unroll 1
        for (int kc = 6; kc < 16; kc++) {
            float4 a0 = x0[kc], a1 = x1[kc];
#pragma unroll
            for (int sub = 0; sub < 4; sub++) {
                int kk = kc * 4 + sub - 24;
                unsigned long long xd0 = dup2(sel4(a0, sub) * s64);
                unsigned long long xd1 = dup2(sel4(a1, sub) * s64);
                const ulonglong2* wa =
                    reinterpret_cast<const ulonglong2*>(cWc1 + kk * 16);
                const ulonglong2* wb =
                    reinterpret_cast<const ulonglong2*>(cWs1 + kk * 32);
#pragma unroll
                for (int j = 0; j < 4; j++) {
                    ulonglong2 wv = wa[j];
                    ffma2(acc[2 * j],          xd0, wv.x);
                    ffma2(acc[2 * j + 1],      xd0, wv.y);
                    ffma2(acc[20 + 2 * j],     xd1, wv.x);
                    ffma2(acc[20 + 2 * j + 1], xd1, wv.y);
                }
#pragma unroll
                for (int j = 0; j < 6; j++) {
                    ulonglong2 wv = wb[j];
                    ffma2(acc[8 + 2 * j],      xd0, wv.x);
                    ffma2(acc[9 + 2 * j],      xd0, wv.y);
                    ffma2(acc[28 + 2 * j],     xd1, wv.x);
                    ffma2(acc[29 + 2 * j],     xd1, wv.y);
                }
            }
        }
    } else {
        // hidden 40..79 = Ws1 cols 24..31 + We1 all (32)
#pragma unroll 1
        for (int kc = 6; kc < 16; kc++) {
            float4 a0 = x0[kc], a1 = x1[kc];
#pragma unroll
            for (int sub = 0; sub < 4; sub++) {
                int kk = kc * 4 + sub - 24;
                unsigned long long xd0 = dup2(sel4(a0, sub) * s64);
                unsigned long long xd1 = dup2(sel4(a1, sub) * s64);
                const ulonglong2* wa =
                    reinterpret_cast<const ulonglong2*>(cWs1 + kk * 32 + 24);
                const ulonglong2* wb =
                    reinterpret_cast<const ulonglong2*>(cWe1 + kk * 32);
#pragma unroll
                for (int j = 0; j < 2; j++) {
                    ulonglong2 wv = wa[j];
                    ffma2(acc[2 * j],          xd0, wv.x);
                    ffma2(acc[2 * j + 1],      xd0, wv.y);
                    ffma2(acc[20 + 2 * j],     xd1, wv.x);
                    ffma2(acc[20 + 2 * j + 1], xd1, wv.y);
                }
#pragma unroll
                for (int j = 0; j < 8; j++) {
                    ulonglong2 wv = wb[j];
                    ffma2(acc[4 + 2 * j],      xd0, wv.x);
                    ffma2(acc[5 + 2 * j],      xd0, wv.y);
                    ffma2(acc[24 + 2 * j],     xd1, wv.x);
                    ffma2(acc[25 + 2 * j],     xd1, wv.y);
                }
            }
        }
    }

    // ---- epilogue: silu * W2, category partial sums, scatter ----
    int s0 = senders[e0];
    int s1 = has1 ? senders[e1] : 0;

#pragma unroll
    for (int eidx = 0; eidx < 2; eidx++) {
        if (eidx == 1 && !has1) break;
        int base = eidx * 20;
        float pA = 0.f, pB = 0.f;
        if (sel == 0) {
            // h 0..15 -> chi, h 16..39 -> sigma
#pragma unroll
            for (int j = 0; j < 8; j++) {
                float2 f = unpk(acc[base + j]);
                pA += siluf(f.x) * cWc2[2 * j] + siluf(f.y) * cWc2[2 * j + 1];
            }
#pragma unroll
            for (int j = 8; j < 20; j++) {
                float2 f = unpk(acc[base + j]);
                pB += siluf(f.x) * cWs2[2 * (j - 8)] + siluf(f.y) * cWs2[2 * (j - 8) + 1];
            }
            pA *= 0.25f;   // 1/sqrt(16)
            pB *= s32;
            int s = eidx ? s1 : s0;
            atomicAdd(&g_chis[s], pA);
            atomicAdd(&g_sigA[s], pB);
        } else {
            // h 40..47 -> sigma, h 48..79 -> eps
#pragma unroll
            for (int j = 0; j < 4; j++) {
                float2 f = unpk(acc[base + j]);
                pA += siluf(f.x) * cWs2[24 + 2 * j] + siluf(f.y) * cWs2[24 + 2 * j + 1];
            }
#pragma unroll
            for (int j = 4; j < 20; j++) {
                float2 f = unpk(acc[base + j]);
                pB += siluf(f.x) * cWe2[2 * (j - 4)] + siluf(f.y) * cWe2[2 * (j - 4) + 1];
            }
            pA *= s32;
            pB *= s32;
            int s = eidx ? s1 : s0;
            atomicAdd(&g_sigA[s], pA);
            atomicAdd(&g_epsA[s], pB);
        }
    }
}

// ---------------------------------------------------------------------------
// Phase 2: per-node charges / pot / vdw / w embedding.
// ---------------------------------------------------------------------------
__global__ __launch_bounds__(256) void k_nodes(
    const int* __restrict__ species, const float* __restrict__ radius,
    const float* __restrict__ hardness, const float* __restrict__ charge_embed,
    float* __restrict__ out_charges, int N)
{
    int n = blockIdx.x * 256 + threadIdx.x;
    float potc = 0.f, vdwc = 0.f;
    if (n < N) {
        int sp = species[n];
        float gamma = fmaf(4.f, radius[sp], 0.5f);
        float hv = hardness[sp];
        float hard = fmaxf(hv, 0.f) + log1pf(__expf(-fabsf(hv)));  // stable softplus
        float chis = g_chis[n];
        float q = -chis / hard;
        potc = 0.5f * (hard + 1.f / gamma) * q * q + chis * q;
        float sgv = sigmf(g_sigA[n]) * 0.15f + 0.15f;
        float epv = sigmf(g_epsA[n]) * 1.7f + 0.3f;
        vdwc = sgv * epv;
        out_charges[n] = q;

        const float s17 = 0.24253562503633297f;  // 1/sqrt(17)
        const float* ce = charge_embed + (size_t)sp * 16;
        float wv[16];
        float qs = q * s17;
#pragma unroll
        for (int j = 0; j < 16; j++) wv[j] = qs * cWw1[j];
#pragma unroll
        for (int i = 0; i < 16; i++) {
            float c = ce[i] * s17;
#pragma unroll
            for (int j = 0; j < 16; j++)
                wv[j] = fmaf(c, cWw1[(1 + i) * 16 + j], wv[j]);
        }
        float4* wout = reinterpret_cast<float4*>(g_w) + (size_t)n * 4;
#pragma unroll
        for (int j = 0; j < 4; j++)
            wout[j] = make_float4(wv[4 * j], wv[4 * j + 1], wv[4 * j + 2], wv[4 * j + 3]);
    }
#pragma unroll
    for (int off = 16; off > 0; off >>= 1) {
        potc += __shfl_down_sync(0xffffffffu, potc, off);
        vdwc += __shfl_down_sync(0xffffffffu, vdwc, off);
    }
    if ((threadIdx.x & 31) == 0) {
        atomicAdd(&g_scal[0], potc);
        atomicAdd(&g_scal[1], vdwc);
    }
}

// ---------------------------------------------------------------------------
// Phase 3: per-edge 80->32->32->32 MLP, envelope, outputs. M=2 edges/thread;
// each layer's k-prefix from smem, k-tail from constant bank.
// ---------------------------------------------------------------------------
__global__ __launch_bounds__(128) void k_phase3(
    const float* __restrict__ x, const float* __restrict__ vectors,
    const float* __restrict__ V, const int* __restrict__ senders,
    const float* __restrict__ Wx1, const float* __restrict__ Wx2,
    const float* __restrict__ Wx3,
    float* __restrict__ out_x, float* __restrict__ out_V,
    float* __restrict__ out_pv, int E, int halfE)
{
    __shared__ __align__(16) float sX1[32 * 32];   // Wx1 rows 0..31
    __shared__ __align__(16) float sX2[12 * 32];   // Wx2 rows 0..11
    __shared__ __align__(16) float sX3[12 * 32];   // Wx3 rows 0..11
    for (int i = threadIdx.x; i < 32 * 32; i += 128) sX1[i] = Wx1[i];
    for (int i = threadIdx.x; i < 12 * 32; i += 128) {
        sX2[i] = Wx2[i];
        sX3[i] = Wx3[i];
    }
    __syncthreads();

    if (blockIdx.x == 0 && threadIdx.x == 0) {
        out_pv[0] = g_scal[0];  // pot (final after k_nodes)
        out_pv[1] = g_scal[1];  // vdw
    }

    int e0 = blockIdx.x * 128 + threadIdx.x;
    if (e0 >= halfE) return;
    int e1 = e0 + halfE;
    bool has1 = (e1 < E);

    const float s80 = 0.11180339887498949f;   // 1/sqrt(80)
    const float s32 = 0.17677669529663689f;   // 1/sqrt(32)

    // acc[0..15] edge0 output pairs, acc[16..31] edge1
    unsigned long long acc[32];
#pragma unroll
    for (int j = 0; j < 32; j++) acc[j] = 0ull;

    const float4* x0 = reinterpret_cast<const float4*>(x) + (size_t)e0 * 16;
    const float4* x1 = reinterpret_cast<const float4*>(x) + (size_t)(has1 ? e1 : e0) * 16;

    // ---- layer 1, k = 0..31 (x) from smem ----
#pragma unroll 1
    for (int kc = 0; kc < 8; kc++) {
        float4 a0 = x0[kc], a1 = x1[kc];
#pragma unroll
        for (int sub = 0; sub < 4; sub++) {
            int k = kc * 4 + sub;
            unsigned long long xd0 = dup2(sel4(a0, sub) * s80);
            unsigned long long xd1 = dup2(sel4(a1, sub) * s80);
            const ulonglong2* w = reinterpret_cast<const ulonglong2*>(sX1 + k * 32);
#pragma unroll
            for (int j = 0; j < 8; j++) {
                ulonglong2 wv = w[j];
                ffma2(acc[2 * j],          xd0, wv.x);
                ffma2(acc[2 * j + 1],      xd0, wv.y);
                ffma2(acc[16 + 2 * j],     xd1, wv.x);
                ffma2(acc[16 + 2 * j + 1], xd1, wv.y);
            }
        }
    }
    // ---- layer 1, k = 32..63 (x) from const ----
#pragma unroll 1
    for (int kc = 8; kc < 16; kc++) {
        float4 a0 = x0[kc], a1 = x1[kc];
#pragma unroll
        for (int sub = 0; sub < 4; sub++) {
            int r = kc * 4 + sub - 32;
            unsigned long long xd0 = dup2(sel4(a0, sub) * s80);
            unsigned long long xd1 = dup2(sel4(a1, sub) * s80);
            const ulonglong2* w = reinterpret_cast<const ulonglong2*>(cX1 + r * 32);
#pragma unroll
            for (int j = 0; j < 8; j++) {
                ulonglong2 wv = w[j];
                ffma2(acc[2 * j],          xd0, wv.x);
                ffma2(acc[2 * j + 1],      xd0, wv.y);
                ffma2(acc[16 + 2 * j],     xd1, wv.x);
                ffma2(acc[16 + 2 * j + 1], xd1, wv.y);
            }
        }
    }
    // ---- layer 1, k = 64..79 (w[sender]) from const ----
    {
        int sd0 = senders[e0];
        int sd1 = has1 ? senders[e1] : sd0;
        const float4* wn0 = reinterpret_cast<const float4*>(g_w) + (size_t)sd0 * 4;
        const float4* wn1 = reinterpret_cast<const float4*>(g_w) + (size_t)sd1 * 4;
#pragma unroll
        for (int kc = 0; kc < 4; kc++) {
            float4 a0 = wn0[kc], a1 = wn1[kc];
#pragma unroll
            for (int sub = 0; sub < 4; sub++) {
                int r = 32 + kc * 4 + sub;   // cX1 rows 32..47
                unsigned long long xd0 = dup2(sel4(a0, sub) * s80);
                unsigned long long xd1 = dup2(sel4(a1, sub) * s80);
                const ulonglong2* w = reinterpret_cast<const ulonglong2*>(cX1 + r * 32);
#pragma unroll
                for (int j = 0; j < 8; j++) {
                    ulonglong2 wv = w[j];
                    ffma2(acc[2 * j],          xd0, wv.x);
                    ffma2(acc[2 * j + 1],      xd0, wv.y);
                    ffma2(acc[16 + 2 * j],     xd1, wv.x);
                    ffma2(acc[16 + 2 * j + 1], xd1, wv.y);
                }
            }
        }
    }

    float h0[32], h1[32];
#pragma unroll
    for (int j = 0; j < 16; j++) {
        float2 f0 = unpk(acc[j]);
        float2 f1 = unpk(acc[16 + j]);
        h0[2 * j]     = siluf(f0.x) * s32;
        h0[2 * j + 1] = siluf(f0.y) * s32;
        h1[2 * j]     = siluf(f1.x) * s32;
        h1[2 * j + 1] = siluf(f1.y) * s32;
    }

    // ---- layer 2: k 0..11 smem, k 12..31 const ----
#pragma unroll
    for (int j = 0; j < 32; j++) acc[j] = 0ull;
#pragma unroll 1
    for (int k = 0; k < 12; k++) {
        unsigned long long xd0 = dup2(h0[k]);
        unsigned long long xd1 = dup2(h1[k]);
        const ulonglong2* w = reinterpret_cast<const ulonglong2*>(sX2 + k * 32);
#pragma unroll
        for (int j = 0; j < 8; j++) {
            ulonglong2 wv = w[j];
            ffma2(acc[2 * j],          xd0, wv.x);
            ffma2(acc[2 * j + 1],      xd0, wv.y);
            ffma2(acc[16 + 2 * j],     xd1, wv.x);
            ffma2(acc[16 + 2 * j + 1], xd1, wv.y);
        }
    }
#pragma unroll 1
    for (int k = 12; k < 32; k++) {
        unsigned long long xd0 = dup2(h0[k]);
        unsigned long long xd1 = dup2(h1[k]);
        const ulonglong2* w = reinterpret_cast<const ulonglong2*>(cX2 + (k - 12) * 32);
#pragma unroll
        for (int j = 0; j < 8; j++) {
            ulonglong2 wv = w[j];
            ffma2(acc[2 * j],          xd0, wv.x);
            ffma2(acc[2 * j + 1],      xd0, wv.y);
            ffma2(acc[16 + 2 * j],     xd1, wv.x);
            ffma2(acc[16 + 2 * j + 1], xd1, wv.y);
        }
    }
#pragma unroll
    for (int j = 0; j < 16; j++) {
        float2 f0 = unpk(acc[j]);
        float2 f1 = unpk(acc[16 + j]);
        h0[2 * j]     = siluf(f0.x) * s32;
        h0[2 * j + 1] = siluf(f0.y) * s32;
        h1[2 * j]     = siluf(f1.x) * s32;
        h1[2 * j + 1] = siluf(f1.y) * s32;
    }

    // ---- layer 3 (no activation): k 0..11 smem, k 12..31 const ----
#pragma unroll
    for (int j = 0; j < 32; j++) acc[j] = 0ull;
#pragma unroll 1
    for (int k = 0; k < 12; k++) {
        unsigned long long xd0 = dup2(h0[k]);
        unsigned long long xd1 = dup2(h1[k]);
        const ulonglong2* w = reinterpret_cast<const ulonglong2*>(sX3 + k * 32);
#pragma unroll
        for (int j = 0; j < 8; j++) {
            ulonglong2 wv = w[j];
            ffma2(acc[2 * j],          xd0, wv.x);
            ffma2(acc[2 * j + 1],      xd0, wv.y);
            ffma2(acc[16 + 2 * j],     xd1, wv.x);
            ffma2(acc[16 + 2 * j + 1], xd1, wv.y);
        }
    }
#pragma unroll 1
    for (int k = 12; k < 32; k++) {
        unsigned long long xd0 = dup2(h0[k]);
        unsigned long long xd1 = dup2(h1[k]);
        const ulonglong2* w = reinterpret_cast<const ulonglong2*>(cX3 + (k - 12) * 32);
#pragma unroll
        for (int j = 0; j < 8; j++) {
            ulonglong2 wv = w[j];
            ffma2(acc[2 * j],          xd0, wv.x);
            ffma2(acc[2 * j + 1],      xd0, wv.y);
            ffma2(acc[16 + 2 * j],     xd1, wv.x);
            ffma2(acc[16 + 2 * j + 1], xd1, wv.y);
        }
    }

    // ---- envelope + outputs for both edges ----
#pragma unroll
    for (int eidx = 0; eidx < 2; eidx++) {
        if (eidx == 1 && !has1) break;
        int e = eidx ? e1 : e0;
        const float* vp = vectors + (size_t)e * 3;
        float vx = vp[0], vy = vp[1], vz = vp[2];
        float u = sqrtf(vx * vx + vy * vy + vz * vz);
        float env = 0.f;
        if (u < 1.f) {
            float u2 = u * u;
            float u3 = u2 * u;
            float u6 = u3 * u3;
            env = 1.f + u6 * (-28.f + u * (48.f - 21.f * u));
        }
        int base = eidx * 16;
        float4* ox = reinterpret_cast<float4*>(out_x) + (size_t)e * 8;
#pragma unroll
        for (int j = 0; j < 8; j++) {
            float2 f0 = unpk(acc[base + 2 * j]);
            float2 f1 = unpk(acc[base + 2 * j + 1]);
            ox[j] = make_float4(env * f0.x, env * f0.y, env * f1.x, env * f1.y);
        }
        const float4* vin = reinterpret_cast<const float4*>(V) + (size_t)e * 4;
        float4* ov = reinterpret_cast<float4*>(out_V) + (size_t)e * 4;
#pragma unroll
        for (int j = 0; j < 4; j++) ov[j] = vin[j];
    }
}

// ---------------------------------------------------------------------------
// Launch. Output layout: x_out[E*32] | V[E*16] | charges[N] | pot | vdw
// ---------------------------------------------------------------------------
extern "C" void kernel_launch(void* const* d_in, const int* in_sizes, int n_in,
                              void* d_out, int out_size) {
    const float* vectors = (const float*)d_in[0];
    const float* x       = (const float*)d_in[1];
    const float* V       = (const float*)d_in[2];
    const int*   senders = (const int*)d_in[3];
    const int*   species = (const int*)d_in[4];
    const float* radius  = (const float*)d_in[5];
    const float* hardness= (const float*)d_in[6];
    const float* cembed  = (const float*)d_in[7];
    const float* Wc1 = (const float*)d_in[8];
    const float* Wc2 = (const float*)d_in[9];
    const float* Ws1 = (const float*)d_in[10];
    const float* Ws2 = (const float*)d_in[11];
    const float* We1 = (const float*)d_in[12];
    const float* We2 = (const float*)d_in[13];
    const float* Ww1 = (const float*)d_in[14];
    const float* Wx1 = (const float*)d_in[15];
    const float* Wx2 = (const float*)d_in[16];
    const float* Wx3 = (const float*)d_in[17];

    const int E = in_sizes[3];
    const int N = in_sizes[4];
    const int halfE = (E + 1) / 2;

    // constant-bank slices (async D2D, graph-capturable)
    cudaMemcpyToSymbolAsync(cWc1, Wc1 + 24 * 16, 40 * 16 * 4, 0, cudaMemcpyDeviceToDevice, 0);
    cudaMemcpyToSymbolAsync(cWs1, Ws1 + 24 * 32, 40 * 32 * 4, 0, cudaMemcpyDeviceToDevice, 0);
    cudaMemcpyToSymbolAsync(cWe1, We1 + 24 * 32, 40 * 32 * 4, 0, cudaMemcpyDeviceToDevice, 0);
    cudaMemcpyToSymbolAsync(cWc2, Wc2, 16 * 4, 0, cudaMemcpyDeviceToDevice, 0);
    cudaMemcpyToSymbolAsync(cWs2, Ws2, 32 * 4, 0, cudaMemcpyDeviceToDevice, 0);
    cudaMemcpyToSymbolAsync(cWe2, We2, 32 * 4, 0, cudaMemcpyDeviceToDevice, 0);
    cudaMemcpyToSymbolAsync(cWw1, Ww1, 17 * 16 * 4, 0, cudaMemcpyDeviceToDevice, 0);
    cudaMemcpyToSymbolAsync(cX1, Wx1 + 32 * 32, 48 * 32 * 4, 0, cudaMemcpyDeviceToDevice, 0);
    cudaMemcpyToSymbolAsync(cX2, Wx2 + 12 * 32, 20 * 32 * 4, 0, cudaMemcpyDeviceToDevice, 0);
    cudaMemcpyToSymbolAsync(cX3, Wx3 + 12 * 32, 20 * 32 * 4, 0, cudaMemcpyDeviceToDevice, 0);

    float* out = (float*)d_out;
    float* out_x       = out;
    float* out_V       = out + (size_t)E * 32;
    float* out_charges = out + (size_t)E * 48;
    float* out_pv      = out + (size_t)E * 48 + N;

    int nb_n  = (N + 255) / 256;
    int nb_e1 = (E + 255) / 256;
    int nb_e3 = (halfE + 127) / 128;

    k_zero<<<nb_n, 256>>>(N);
    k_phase1<<<nb_e1, 256>>>(x, senders, Wc1, Ws1, We1, E);
    k_nodes<<<nb_n, 256>>>(species, radius, hardness, cembed, out_charges, N);
    k_phase3<<<nb_e3, 128>>>(x, vectors, V, senders, Wx1, Wx2, Wx3,
                             out_x, out_V, out_pv, E, halfE);
}